// round 8
// baseline (speedup 1.0000x reference)
#include <cuda_runtime.h>
#include <cuda_bf16.h>
#include <math.h>
#include <stdint.h>

#define BATCH 4096
#define B2    8192
#define NTILE 2080                  // triangular 128x128 tiles per branch
#define LSE_BLOCKS 128
#define GRID_P 296                  // persistent CTAs (2 per SM) -- must all be resident
#define WU 2
#define WI 3
#define WTOT (NTILE * (WU + WI))    // 10400
#define LN2F 0.6931471805599453f
#define ROOT_S 2.68579135f          // sqrt(log2(e)/T) folded into operands
#define UBASE 8.0f                  // fixed user-branch basis (logits in +-7.22)

#define TROW 272
#define TILE_SM (128 * TROW)        // 34816 B
#define SMEM_RED 6144
#define SMEM_REQ (3 * TILE_SM + SMEM_RED)

__device__ __align__(256) __nv_bfloat16 g_Y[2][B2 * 128];
__device__ float g_s[2][64][64][128];
__device__ float g_mv[2][64][64][128];
__device__ float g_lse_partial[LSE_BLOCKS];
__device__ float g_pos_partial[GRID_P];
// monotonic ticket counters: never reset, replay-safe
__device__ int g_bar1 = 0, g_bar2 = 0, g_cnt = 0;

// ---------------------------------------------------------------------------
__device__ __forceinline__ uint32_t smem_u32(const void* p) {
    uint32_t a;
    asm("{ .reg .u64 t; cvta.to.shared.u64 t, %1; cvt.u32.u64 %0, t; }" : "=r"(a) : "l"(p));
    return a;
}
__device__ __forceinline__ float ex2(float x) {
    float y; asm("ex2.approx.f32 %0, %1;" : "=f"(y) : "f"(x)); return y;
}
__device__ __forceinline__ float lg2(float x) {
    float y; asm("lg2.approx.f32 %0, %1;" : "=f"(y) : "f"(x)); return y;
}
__device__ __forceinline__ void ldsm4(uint32_t* r, uint32_t addr) {
    asm volatile("ldmatrix.sync.aligned.m8n8.x4.shared.b16 {%0,%1,%2,%3}, [%4];"
        : "=r"(r[0]), "=r"(r[1]), "=r"(r[2]), "=r"(r[3]) : "r"(addr));
}
__device__ __forceinline__ void mma16816(float* c, const uint32_t* a,
                                         uint32_t b0, uint32_t b1) {
    asm volatile("mma.sync.aligned.m16n8k16.row.col.f32.bf16.bf16.f32 "
        "{%0,%1,%2,%3}, {%4,%5,%6,%7}, {%8,%9}, {%0,%1,%2,%3};"
        : "+f"(c[0]), "+f"(c[1]), "+f"(c[2]), "+f"(c[3])
        : "r"(a[0]), "r"(a[1]), "r"(a[2]), "r"(a[3]), "r"(b0), "r"(b1));
}
#define CP16(dst, src) \
    asm volatile("cp.async.cg.shared.global [%0], [%1], 16;" :: "r"(dst), "l"(src))
#define CP_COMMIT() asm volatile("cp.async.commit_group;" ::: "memory")
#define CP_WAIT0()  asm volatile("cp.async.wait_group 0;" ::: "memory")

// Grid-wide ticket barrier: monotonic counter, no reset, graph-replay safe.
__device__ __forceinline__ void grid_barrier(int* ctr) {
    __shared__ int target;
    __syncthreads();
    __threadfence();
    if (threadIdx.x == 0) {
        int t = atomicAdd(ctr, 1);
        target = (t / GRID_P + 1) * GRID_P;
    }
    __syncthreads();
    if (threadIdx.x == 0) {
        volatile int* v = ctr;
        while (*v < target) __nanosleep(64);
    }
    __syncthreads();
    __threadfence();
}

// ---------------------------------------------------------------------------
template<int NC16>
__device__ __forceinline__ void stage_tile(uint32_t sdst,
                                           const __nv_bfloat16* __restrict__ Y,
                                           int row0, int tid)
{
    #pragma unroll
    for (int i = 0; i < (128 * NC16) / 256; i++) {
        int l   = i * 256 + tid;
        int row = l / NC16;
        int col = l - row * NC16;
        uint32_t dst = sdst + (uint32_t)(row * TROW + col * 16);
        const char* src = (const char*)(Y + (size_t)(row0 + row) * 128) + col * 16;
        CP16(dst, src);
    }
}

template<bool FULL>
__device__ __forceinline__ void mainloop(float acc[2][8][4],
                                         uint32_t aAddr, uint32_t bAddr)
{
    #pragma unroll
    for (int kk = 0; kk < 4; kk++) {
        uint32_t ah[2][4], al[2][4];
        ldsm4(ah[0], aAddr + kk * 32);
        ldsm4(ah[1], aAddr + 16 * TROW + kk * 32);
        if (FULL) {
            ldsm4(al[0], aAddr + 128 + kk * 32);
            ldsm4(al[1], aAddr + 16 * TROW + 128 + kk * 32);
        }
        #pragma unroll
        for (int ng = 0; ng < 4; ng++) {
            uint32_t bh[4], bl[4];
            ldsm4(bh, bAddr + ng * 16 * TROW + kk * 32);
            if (FULL) ldsm4(bl, bAddr + ng * 16 * TROW + 128 + kk * 32);
            #pragma unroll
            for (int mf = 0; mf < 2; mf++) {
                mma16816(acc[mf][ng * 2],     ah[mf], bh[0], bh[1]);
                mma16816(acc[mf][ng * 2 + 1], ah[mf], bh[2], bh[3]);
                if (FULL) {
                    mma16816(acc[mf][ng * 2],     al[mf], bh[0], bh[1]);
                    mma16816(acc[mf][ng * 2 + 1], al[mf], bh[2], bh[3]);
                    mma16816(acc[mf][ng * 2],     ah[mf], bl[0], bl[1]);
                    mma16816(acc[mf][ng * 2 + 1], ah[mf], bl[2], bl[3]);
                }
            }
        }
    }
}

__device__ __forceinline__ void decode_tile(int t, int& r, int& c)
{
    r = (int)((129.0f - sqrtf(16641.0f - 8.0f * (float)t)) * 0.5f);
    while ((r + 1) * (129 - (r + 1)) / 2 <= t) r++;
    while (r * (129 - r) / 2 > t) r--;
    c = r + (t - r * (129 - r) / 2);
}

// ---------------------------------------------------------------------------
// Fused persistent kernel: prep -> barrier -> tiles -> barrier -> combine+loss
// ---------------------------------------------------------------------------
__global__ void __launch_bounds__(256, 2) fused_kernel(
    const int* __restrict__ u_list, const int* __restrict__ i_list,
    const float* __restrict__ u1t, const float* __restrict__ i1t,
    const float* __restrict__ u2t, const float* __restrict__ i2t,
    float* __restrict__ out)
{
    extern __shared__ unsigned char dsm[];
    float* sRowM = (float*)(dsm + 3 * TILE_SM);
    float* sColM = (float*)(dsm + 3 * TILE_SM + 1024);
    float* sRowS = (float*)(dsm + 3 * TILE_SM + 3072);
    float* sColS = (float*)(dsm + 3 * TILE_SM + 4096);

    int tid  = threadIdx.x;
    int lane = tid & 31;
    int wid  = tid >> 5;

    // ==================== Phase 0: prep ====================
    {
        float pdsum = 0.f;
        for (int w = blockIdx.x * 8 + wid; w < 2 * BATCH; w += GRID_P * 8) {
            int branch = w >> 12;
            int i      = w & (BATCH - 1);
            int idx = (branch ? i_list : u_list)[i];
            const float* t1 = branch ? i1t : u1t;
            const float* t2 = branch ? i2t : u2t;

            float2 a = ((const float2*)(t1 + (size_t)idx * 64))[lane];
            float2 b = ((const float2*)(t2 + (size_t)idx * 64))[lane];

            if (branch == 0) {
                float na = a.x * a.x + a.y * a.y;
                float nb = b.x * b.x + b.y * b.y;
                #pragma unroll
                for (int o = 16; o; o >>= 1) {
                    na += __shfl_xor_sync(0xffffffffu, na, o);
                    nb += __shfl_xor_sync(0xffffffffu, nb, o);
                }
                float ia = rsqrtf(na), ib = rsqrtf(nb);
                a.x *= ia; a.y *= ia;
                b.x *= ib; b.y *= ib;
            }
            pdsum += a.x * b.x + a.y * b.y;

            __nv_bfloat16* Y = g_Y[branch];
            #pragma unroll
            for (int which = 0; which < 2; which++) {
                float2 v = which ? b : a;
                int row  = which ? (BATCH + i) : i;
                float yx = v.x * ROOT_S, yy = v.y * ROOT_S;
                __nv_bfloat16 hx = __float2bfloat16(yx);
                __nv_bfloat16 hy = __float2bfloat16(yy);
                __nv_bfloat16 lx = __float2bfloat16(yx - __bfloat162float(hx));
                __nv_bfloat16 ly = __float2bfloat16(yy - __bfloat162float(hy));
                __nv_bfloat162* rp = (__nv_bfloat162*)(Y + (size_t)row * 128);
                rp[lane]      = __nv_bfloat162(hx, hy);
                rp[32 + lane] = __nv_bfloat162(lx, ly);
            }
        }
        #pragma unroll
        for (int o = 16; o; o >>= 1) pdsum += __shfl_xor_sync(0xffffffffu, pdsum, o);
        float* sp_ = sRowM;   // reuse reduction smem during prep
        if (lane == 0) sp_[wid] = pdsum;
        __syncthreads();
        if (tid == 0) {
            float s = 0.f;
            #pragma unroll
            for (int k2 = 0; k2 < 8; k2++) s += sp_[k2];
            g_pos_partial[blockIdx.x] = s;
        }
    }

    grid_barrier(&g_bar1);

    // ==================== Phase 1: tiles ====================
    {
        int wy  = wid >> 1;
        int wx  = wid & 1;
        int gid = lane >> 2;
        int tig = lane & 3;

        int k   = blockIdx.x;
        int wlo = (int)(((long long)k * WTOT) / GRID_P);
        int whi = (int)(((long long)(k + 1) * WTOT) / GRID_P);
        int u0 = (wlo + 1) >> 1, u1 = (whi + 1) >> 1;
        if (u1 > NTILE) u1 = NTILE;
        if (u0 > u1) u0 = u1;
        int lo = wlo - NTILE * WU; if (lo < 0) lo = 0;
        int hi = whi - NTILE * WU; if (hi < 0) hi = 0;
        int i0 = (lo + 2) / 3, i1 = (hi + 2) / 3;
        if (i1 > NTILE) i1 = NTILE;
        if (i0 > i1) i0 = i1;
        int nu = u1 - u0, ni = i1 - i0;
        int n = nu + ni;

        uint32_t sAu = smem_u32(dsm);
        uint32_t sB0 = sAu + TILE_SM;
        uint32_t aAddr0 = sAu + (uint32_t)((wy * 32 + (lane & 7) + ((lane >> 3) & 1) * 8) * TROW
                                           + ((lane >> 4) & 1) * 16);
        uint32_t bOff   = (uint32_t)((wx * 64 + ((lane >> 4) & 1) * 8 + (lane & 7)) * TROW
                                     + ((lane >> 3) & 1) * 16);

        auto get_bt = [&](int j, int& b_, int& t_) {
            if (j < nu) { b_ = 0; t_ = u0 + j; }
            else        { b_ = 1; t_ = i0 + (j - nu); }
        };

        if (n > 0) {
            int b, t, r, c;
            get_bt(0, b, t);
            decode_tile(t, r, c);

            if (b == 0) { stage_tile<8>(sAu, g_Y[0], r * 128, tid);
                          stage_tile<8>(sB0, g_Y[0], c * 128, tid); }
            else        { stage_tile<16>(sAu, g_Y[1], r * 128, tid);
                          stage_tile<16>(sB0, g_Y[1], c * 128, tid); }
            CP_COMMIT();

            int buf = 0;
            for (int j = 0; j < n; j++) {
                int bn = 0, tn = 0, rn = 0, cn = 0;
                bool have_next = (j + 1 < n);
                if (have_next) { get_bt(j + 1, bn, tn); decode_tile(tn, rn, cn); }

                CP_WAIT0();
                __syncthreads();

                if (have_next) {
                    uint32_t sBn = sAu + TILE_SM + (uint32_t)((buf ^ 1) * TILE_SM);
                    if (bn == 0) stage_tile<8>(sBn, g_Y[0], cn * 128, tid);
                    else         stage_tile<16>(sBn, g_Y[1], cn * 128, tid);
                    CP_COMMIT();
                }

                uint32_t bAddr = sAu + TILE_SM + (uint32_t)(buf * TILE_SM) + bOff;

                float acc[2][8][4];
                #pragma unroll
                for (int mf = 0; mf < 2; mf++)
                    #pragma unroll
                    for (int nf = 0; nf < 8; nf++)
                        #pragma unroll
                        for (int jj = 0; jj < 4; jj++) acc[mf][nf][jj] = 0.f;

                if (b == 0) mainloop<false>(acc, aAddr0, bAddr);
                else        mainloop<true >(acc, aAddr0, bAddr);

                __syncthreads();

                if (have_next && (bn != b || rn != r)) {
                    if (bn == 0) stage_tile<8>(sAu, g_Y[0], rn * 128, tid);
                    else         stage_tile<16>(sAu, g_Y[1], rn * 128, tid);
                    CP_COMMIT();
                }

                bool isdiag = (r == c);
                if (isdiag) {
                    #pragma unroll
                    for (int mf = 0; mf < 2; mf++)
                        #pragma unroll
                        for (int nf = 0; nf < 8; nf++)
                            #pragma unroll
                            for (int jj = 0; jj < 4; jj++) {
                                int rl = wy * 32 + mf * 16 + ((jj >> 1) & 1) * 8 + gid;
                                int cl = wx * 64 + nf * 8 + tig * 2 + (jj & 1);
                                if (rl == cl) acc[mf][nf][jj] = -1e30f;
                            }
                }

                if (b == 0) {
                    // user: fixed basis, single exp pass
                    #pragma unroll
                    for (int mf = 0; mf < 2; mf++)
                        #pragma unroll
                        for (int nf = 0; nf < 8; nf++)
                            #pragma unroll
                            for (int jj = 0; jj < 4; jj++)
                                acc[mf][nf][jj] = ex2(acc[mf][nf][jj] - UBASE);

                    #pragma unroll
                    for (int mf = 0; mf < 2; mf++)
                        #pragma unroll
                        for (int h = 0; h < 2; h++) {
                            float v = 0.f;
                            #pragma unroll
                            for (int nf = 0; nf < 8; nf++)
                                v += acc[mf][nf][h * 2] + acc[mf][nf][h * 2 + 1];
                            v += __shfl_xor_sync(0xffffffffu, v, 1);
                            v += __shfl_xor_sync(0xffffffffu, v, 2);
                            if (tig == 0)
                                sRowS[(wy * 32 + mf * 16 + h * 8 + gid) * 2 + wx] = v;
                        }
                    if (!isdiag) {
                        #pragma unroll
                        for (int nf = 0; nf < 8; nf++)
                            #pragma unroll
                            for (int q = 0; q < 2; q++) {
                                float v = 0.f;
                                #pragma unroll
                                for (int mf = 0; mf < 2; mf++)
                                    #pragma unroll
                                    for (int h = 0; h < 2; h++)
                                        v += acc[mf][nf][h * 2 + q];
                                v += __shfl_xor_sync(0xffffffffu, v, 4);
                                v += __shfl_xor_sync(0xffffffffu, v, 8);
                                v += __shfl_xor_sync(0xffffffffu, v, 16);
                                if (gid == 0)
                                    sColS[(wx * 64 + nf * 8 + tig * 2 + q) * 4 + wy] = v;
                            }
                    }
                    __syncthreads();
                    if (tid < 128) {
                        g_s[0][r][c][tid]  = sRowS[tid * 2] + sRowS[tid * 2 + 1];
                        g_mv[0][r][c][tid] = UBASE;
                        if (!isdiag) {
                            g_s[0][c][r][tid]  = sColS[tid * 4] + sColS[tid * 4 + 1]
                                               + sColS[tid * 4 + 2] + sColS[tid * 4 + 3];
                            g_mv[0][c][r][tid] = UBASE;
                        }
                    }
                    __syncthreads();
                } else {
                    // item: exact per-row / per-col bases
                    #pragma unroll
                    for (int mf = 0; mf < 2; mf++)
                        #pragma unroll
                        for (int h = 0; h < 2; h++) {
                            float v = -1e30f;
                            #pragma unroll
                            for (int nf = 0; nf < 8; nf++)
                                v = fmaxf(v, fmaxf(acc[mf][nf][h * 2],
                                                   acc[mf][nf][h * 2 + 1]));
                            v = fmaxf(v, __shfl_xor_sync(0xffffffffu, v, 1));
                            v = fmaxf(v, __shfl_xor_sync(0xffffffffu, v, 2));
                            if (tig == 0)
                                sRowM[(wy * 32 + mf * 16 + h * 8 + gid) * 2 + wx] = v;
                        }
                    #pragma unroll
                    for (int nf = 0; nf < 8; nf++)
                        #pragma unroll
                        for (int q = 0; q < 2; q++) {
                            float v = -1e30f;
                            #pragma unroll
                            for (int mf = 0; mf < 2; mf++)
                                #pragma unroll
                                for (int h = 0; h < 2; h++)
                                    v = fmaxf(v, acc[mf][nf][h * 2 + q]);
                            v = fmaxf(v, __shfl_xor_sync(0xffffffffu, v, 4));
                            v = fmaxf(v, __shfl_xor_sync(0xffffffffu, v, 8));
                            v = fmaxf(v, __shfl_xor_sync(0xffffffffu, v, 16));
                            if (gid == 0)
                                sColM[(wx * 64 + nf * 8 + tig * 2 + q) * 4 + wy] = v;
                        }
                    __syncthreads();

                    float rm[2][2], cm[8][2];
                    #pragma unroll
                    for (int mf = 0; mf < 2; mf++)
                        #pragma unroll
                        for (int h = 0; h < 2; h++) {
                            int row = wy * 32 + mf * 16 + h * 8 + gid;
                            rm[mf][h] = fmaxf(sRowM[row * 2], sRowM[row * 2 + 1]);
                        }
                    #pragma unroll
                    for (int nf = 0; nf < 8; nf++)
                        #pragma unroll
                        for (int q = 0; q < 2; q++) {
                            int col = wx * 64 + nf * 8 + tig * 2 + q;
                            cm[nf][q] = fmaxf(fmaxf(sColM[col * 4], sColM[col * 4 + 1]),
                                              fmaxf(sColM[col * 4 + 2], sColM[col * 4 + 3]));
                        }

                    #pragma unroll
                    for (int mf = 0; mf < 2; mf++)
                        #pragma unroll
                        for (int h = 0; h < 2; h++) {
                            float v = 0.f, mmx = rm[mf][h];
                            #pragma unroll
                            for (int nf = 0; nf < 8; nf++)
                                v += ex2(acc[mf][nf][h * 2] - mmx)
                                   + ex2(acc[mf][nf][h * 2 + 1] - mmx);
                            v += __shfl_xor_sync(0xffffffffu, v, 1);
                            v += __shfl_xor_sync(0xffffffffu, v, 2);
                            if (tig == 0)
                                sRowS[(wy * 32 + mf * 16 + h * 8 + gid) * 2 + wx] = v;
                        }
                    if (!isdiag) {
                        #pragma unroll
                        for (int nf = 0; nf < 8; nf++)
                            #pragma unroll
                            for (int q = 0; q < 2; q++) {
                                float v = 0.f, mmx = cm[nf][q];
                                #pragma unroll
                                for (int mf = 0; mf < 2; mf++)
                                    #pragma unroll
                                    for (int h = 0; h < 2; h++)
                                        v += ex2(acc[mf][nf][h * 2 + q] - mmx);
                                v += __shfl_xor_sync(0xffffffffu, v, 4);
                                v += __shfl_xor_sync(0xffffffffu, v, 8);
                                v += __shfl_xor_sync(0xffffffffu, v, 16);
                                if (gid == 0)
                                    sColS[(wx * 64 + nf * 8 + tig * 2 + q) * 4 + wy] = v;
                            }
                    }
                    __syncthreads();
                    if (tid < 128) {
                        g_s[1][r][c][tid]  = sRowS[tid * 2] + sRowS[tid * 2 + 1];
                        g_mv[1][r][c][tid] = fmaxf(sRowM[tid * 2], sRowM[tid * 2 + 1]);
                        if (!isdiag) {
                            g_s[1][c][r][tid]  = sColS[tid * 4] + sColS[tid * 4 + 1]
                                               + sColS[tid * 4 + 2] + sColS[tid * 4 + 3];
                            g_mv[1][c][r][tid] = fmaxf(fmaxf(sColM[tid * 4], sColM[tid * 4 + 1]),
                                                       fmaxf(sColM[tid * 4 + 2], sColM[tid * 4 + 3]));
                        }
                    }
                    __syncthreads();
                }

                b = bn; t = tn; r = rn; c = cn;
                buf ^= 1;
            }
        }
    }

    grid_barrier(&g_bar2);

    // ==================== Phase 2: combine + finalize ====================
    if (blockIdx.x < LSE_BLOCKS) {
        int b  = blockIdx.x >> 6;
        int rt = blockIdx.x & 63;
        __shared__ float sOut[4];
        __shared__ int sLast;

        float lse = 0.f;
        if (tid < 128) {
            float m = -1e30f, s = 0.f;
            #pragma unroll 8
            for (int ct = 0; ct < 64; ct++) {
                float mc = g_mv[b][rt][ct][tid];
                float sc = g_s[b][rt][ct][tid];
                float mn = fmaxf(m, mc);
                s = s * ex2(m - mn) + sc * ex2(mc - mn);
                m = mn;
            }
            lse = LN2F * (m + lg2(s));
            #pragma unroll
            for (int o = 16; o; o >>= 1) lse += __shfl_xor_sync(0xffffffffu, lse, o);
            if (lane == 0) sOut[wid] = lse;
        }
        __syncthreads();
        if (tid == 0) {
            g_lse_partial[blockIdx.x] = sOut[0] + sOut[1] + sOut[2] + sOut[3];
            __threadfence();
            int t = atomicAdd(&g_cnt, 1);
            sLast = (((t + 1) % LSE_BLOCKS) == 0) ? 1 : 0;
        }
        __syncthreads();

        if (sLast) {
            __threadfence();
            float v = 0.f;
            if (tid < 128) {
                v = g_lse_partial[tid] * (1.0f / (float)B2);
                for (int i = tid; i < GRID_P; i += 128)
                    v -= g_pos_partial[i] * (1.0f / ((float)BATCH * 0.2f));
                #pragma unroll
                for (int o = 16; o; o >>= 1) v += __shfl_xor_sync(0xffffffffu, v, o);
            }
            __shared__ float sF[4];
            if (tid < 128 && lane == 0) sF[wid] = v;
            __syncthreads();
            if (tid == 0) out[0] = sF[0] + sF[1] + sF[2] + sF[3];
        }
    }
}

extern "C" void kernel_launch(void* const* d_in, const int* in_sizes, int n_in,
                              void* d_out, int out_size)
{
    const int*   u_list = (const int*)  d_in[0];
    const int*   i_list = (const int*)  d_in[1];
    const float* u1     = (const float*)d_in[2];
    const float* i1     = (const float*)d_in[3];
    const float* u2     = (const float*)d_in[4];
    const float* i2     = (const float*)d_in[5];
    float* out = (float*)d_out;

    cudaFuncSetAttribute(fused_kernel, cudaFuncAttributeMaxDynamicSharedMemorySize,
                         SMEM_REQ);

    fused_kernel<<<GRID_P, 256, SMEM_REQ>>>(u_list, i_list, u1, i1, u2, i2, out);
}